// round 16
// baseline (speedup 1.0000x reference)
#include <cuda_runtime.h>
#include <cuda_fp16.h>
#include <cstdint>
#include <cstring>

#define SQ 1024
#define BA 64
#define IN 256
#define HD 512
#define G4 2048
#define WPAD 520

// ---------------- device scratch ----------------
__device__ __align__(16) float g_BIAS[G4];
__device__ __align__(16) __half g_WXh[G4 * IN];            // [n][i] fp16
__device__ __align__(16) __half g_Xh[(size_t)65536 * IN];  // [m=(s<<6)|b][i] fp16
__device__ __align__(16) __half g_WHh[32 * 64 * 512];      // [hg][r'=jl*4+g][k] fp16
__device__ __align__(16) float g_XG[(size_t)SQ * BA * G4];
__device__ __align__(16) uint32_t g_H32[2][BA * HD];       // tagged h: (tag<<16)|fp16

// ---------------- helpers ----------------
__device__ __forceinline__ uint32_t smem_u32(const void* p) {
    uint32_t a;
    asm("{ .reg .u64 t; cvta.to.shared.u64 t, %1; cvt.u32.u64 %0, t; }" : "=r"(a) : "l"(p));
    return a;
}
__device__ __forceinline__ void ldsm4(uint32_t* r, uint32_t a) {
    asm volatile("ldmatrix.sync.aligned.m8n8.x4.shared.b16 {%0,%1,%2,%3}, [%4];"
                 : "=r"(r[0]), "=r"(r[1]), "=r"(r[2]), "=r"(r[3]) : "r"(a));
}
__device__ __forceinline__ void ldsm2(uint32_t* r, uint32_t a) {
    asm volatile("ldmatrix.sync.aligned.m8n8.x2.shared.b16 {%0,%1}, [%2];"
                 : "=r"(r[0]), "=r"(r[1]) : "r"(a));
}
__device__ __forceinline__ void mma16816h(float* d, const uint32_t* a, const uint32_t* b) {
    asm volatile("mma.sync.aligned.m16n8k16.row.col.f32.f16.f16.f32 "
                 "{%0,%1,%2,%3}, {%4,%5,%6,%7}, {%8,%9}, {%0,%1,%2,%3};"
                 : "+f"(d[0]), "+f"(d[1]), "+f"(d[2]), "+f"(d[3])
                 : "r"(a[0]), "r"(a[1]), "r"(a[2]), "r"(a[3]), "r"(b[0]), "r"(b[1]));
}
__device__ __forceinline__ float tanh_fast(float x) {
    float t = __expf(2.f * x);
    return __fdividef(t - 1.f, t + 1.f);
}

// ---------------- prep ----------------
__global__ void prep_kernel(
    const float* Wxi, const float* bxi, const float* Whi, const float* bhi,
    const float* Wxf, const float* bxf, const float* Whf, const float* bhf,
    const float* Wxo, const float* bxo, const float* Who, const float* bho,
    const float* Wxc, const float* bxc, const float* Whc, const float* bhc)
{
    const float* Wx[4] = {Wxi, Wxf, Wxo, Wxc};
    const float* bx[4] = {bxi, bxf, bxo, bxc};
    const float* Wh[4] = {Whi, Whf, Who, Whc};
    const float* bh[4] = {bhi, bhf, bho, bhc};
    long idx = (long)blockIdx.x * 256 + threadIdx.x;

    if (idx < 524288L) {                       // WX fp16, [n][i]
        int i = (int)(idx & 255), n = (int)(idx >> 8);
        int g = n >> 9, j = n & 511;
        g_WXh[idx] = __float2half_rn(Wx[g][(size_t)j * IN + i]);
        return;
    }
    idx -= 524288L;
    if (idx < 2048L) {
        int g = (int)(idx >> 9), j = (int)(idx & 511);
        g_BIAS[idx] = bx[g][j] + bh[g][j];
        return;
    }
    idx -= 2048L;
    if (idx < 1048576L) {                      // WH fp16, row r' = jl*4 + g
        int k = (int)(idx & 511);
        int rp = (int)((idx >> 9) & 63);
        int hg = (int)(idx >> 15);
        int jl = rp >> 2, g = rp & 3;
        int j = hg * 16 + jl;
        g_WHh[idx] = __float2half_rn(Wh[g][(size_t)j * HD + k]);
        return;
    }
    idx -= 1048576L;
    if (idx < 65536L) {                        // tag-init BOTH h buffers each launch
        ((uint32_t*)g_H32)[idx] = 0xFFFF0000u; // tag=0xFFFF, h=0
        return;
    }
}

// ---------------- x -> fp16, layout [(s<<6)|b][i] ----------------
__global__ __launch_bounds__(256) void xsplit_kernel(const float* __restrict__ x)
{
    long idx = (long)blockIdx.x * 256 + threadIdx.x;
    long e = idx * 4;
    int i = (int)(e & 255);
    int s = (int)((e >> 8) & 1023);
    int b = (int)(e >> 18);
    float4 v = __ldg((const float4*)(x + e));
    __half h[4] = {__float2half_rn(v.x), __float2half_rn(v.y),
                   __float2half_rn(v.z), __float2half_rn(v.w)};
    size_t off = (((size_t)((s << 6) | b)) << 8) + i;
    *(uint2*)(g_Xh + off) = *(uint2*)h;
}

// ---------------- xproj: single-term fp16 HMMA (proven R10) ----------------
#define XPAD 136
#define XS_A 0
#define XS_B (128 * XPAD * 2)
#define XSMEM_BYTES (2 * 128 * XPAD * 2)

__global__ __launch_bounds__(256, 1) void xproj_hmma_kernel()
{
    extern __shared__ char sm[];
    int tid = threadIdx.x;
    int wid = tid >> 5, lane = tid & 31;
    int n0 = blockIdx.x * 128, m0 = blockIdx.y * 128;
    int mh = wid & 1, nh = wid >> 1;

    uint32_t smb = smem_u32(sm);
    int arow = lane & 15, ak = (lane >= 16) ? 8 : 0;
    uint32_t aB = smb + XS_A + ((mh * 64 + arow) * XPAD + ak) * 2;
    int brow = lane & 7, bk = (lane & 8) ? 8 : 0;
    uint32_t bB = smb + XS_B + ((nh * 32 + brow) * XPAD + bk) * 2;

    float d[4][4][4];
#pragma unroll
    for (int mi = 0; mi < 4; mi++)
#pragma unroll
        for (int ni = 0; ni < 4; ni++)
#pragma unroll
            for (int q = 0; q < 4; q++) d[mi][ni][q] = 0.f;

    int fr = tid >> 1, fh = (tid & 1) * 64;
#pragma unroll
    for (int kc = 0; kc < 2; kc++) {
        int k0 = kc * 128;
        {
            const uint4* sa = (const uint4*)(g_Xh + (((size_t)(m0 + fr)) << 8) + k0 + fh);
            const uint4* sb = (const uint4*)(g_WXh + (((size_t)(n0 + fr)) << 8) + k0 + fh);
            uint4* da4 = (uint4*)(sm + XS_A + (fr * XPAD + fh) * 2);
            uint4* db4 = (uint4*)(sm + XS_B + (fr * XPAD + fh) * 2);
#pragma unroll
            for (int c = 0; c < 8; c++) {
                da4[c] = __ldg(sa + c);
                db4[c] = __ldg(sb + c);
            }
        }
        __syncthreads();
#pragma unroll
        for (int ks = 0; ks < 8; ks++) {
            uint32_t ko = (uint32_t)ks * 32;
            uint32_t ah[4][4], bh[4][2];
#pragma unroll
            for (int mi = 0; mi < 4; mi++)
                ldsm4(ah[mi], aB + mi * (16 * XPAD * 2) + ko);
#pragma unroll
            for (int ni = 0; ni < 4; ni++)
                ldsm2(bh[ni], bB + ni * (8 * XPAD * 2) + ko);
#pragma unroll
            for (int mi = 0; mi < 4; mi++)
#pragma unroll
                for (int ni = 0; ni < 4; ni++)
                    mma16816h(d[mi][ni], ah[mi], bh[ni]);
        }
        __syncthreads();
    }

    int row_l = lane >> 2, col_l = (lane & 3) * 2;
#pragma unroll
    for (int mi = 0; mi < 4; mi++)
#pragma unroll
        for (int ni = 0; ni < 4; ni++) {
            int gr = m0 + mh * 64 + mi * 16 + row_l;
            int gc = n0 + nh * 32 + ni * 8 + col_l;
            float2 bb = *(const float2*)(g_BIAS + gc);
            float* o = g_XG + (size_t)gr * G4 + gc;
            *(float2*)o = make_float2(d[mi][ni][0] + bb.x, d[mi][ni][1] + bb.y);
            *(float2*)(o + 8 * G4) = make_float2(d[mi][ni][2] + bb.x, d[mi][ni][3] + bb.y);
        }
}

// ---------------- lstm: tagged-data signaling, 8 warps, full-K per warp ----------------
// 128 CTAs = 4 bg x 32 hg; 256 thr = 8 warps = 4 mw x 2 nh; K=512 per warp.
// Sync per step: tag-poll (spread addresses) + 2 CTA barriers. No counters/atomics/fences.
#define OFF_SCR (16 * WPAD * 2 + 64)
#define LSMEM_BYTES (64 * WPAD * 2)

__global__ __launch_bounds__(256, 1) void lstm_hmma_kernel(float* __restrict__ out)
{
    extern __shared__ char sm[];
    int tid = threadIdx.x;
    int wid = tid >> 5, lane = tid & 31;
    int bg = blockIdx.x >> 5;
    int hg = blockIdx.x & 31;
    int mw = wid >> 1;           // M quarter (16 rows = 4 jl x 4 gates)
    int nh = wid & 1;            // N half (8 batches)

    {   // stage W [64][WPAD] (256 threads x 256B)
        int r = tid >> 2, part = tid & 3;
        const uint4* s4 = (const uint4*)(g_WHh + ((size_t)(hg * 64 + r) << 9) + part * 128);
        uint4* d4 = (uint4*)(sm + (r * WPAD + part * 128) * 2);
#pragma unroll
        for (int i = 0; i < 16; i++) d4[i] = s4[i];
    }
    __syncthreads();

    uint32_t smb = smem_u32(sm);
    uint32_t areg[32][4];
    {   // full-K A frags -> registers (once)
        int arow = lane & 15, ako = (lane >= 16) ? 8 : 0;
        uint32_t aB = smb + ((mw * 16 + arow) * WPAD + ako) * 2;
#pragma unroll
        for (int kt = 0; kt < 32; kt++) ldsm4(areg[kt], aB + kt * 32);
    }
    __syncthreads();   // W staging region now reused as HH + scratch

    // B double-tile ldsm4: mats 0,1 = k-tile lo; mats 2,3 = k-tile hi (same n rows)
    uint32_t bB = smb + ((nh * 8 + (lane & 7)) * WPAD
                         + ((lane & 8) ? 8 : 0) + ((lane >= 16) ? 16 : 0)) * 2;

    float* scr = (float*)(sm + OFF_SCR) + wid * 144;   // per-warp [16][9]
    int rr = lane >> 2, cc = (lane & 3) * 2;

    int jlq = lane >> 3, bq = lane & 7;
    int jl = mw * 4 + jlq, b = nh * 8 + bq;
    int hwr = (bg * 16 + b) * HD + hg * 16 + jl;       // out index
    uint32_t* hdst0 = &g_H32[0][hwr];
    uint32_t* hdst1 = &g_H32[1][hwr];
    float c_reg = 0.f;

    int frow = tid >> 4, fch = (tid & 15) * 32;        // fill: 32 tagged words/thread
    long fuse = 20000000L;                             // lifetime poll budget

    for (int s = 0; s < SQ; s++) {
        // xg prefetch (DRAM latency hidden behind tag-poll)
        const float* xgr = g_XG + (((size_t)(s * 64 + bg * 16 + b)) << 11) + hg * 16 + jl;
        float xgi = __ldg(xgr);
        float xgf = __ldg(xgr + 512);
        float xgo = __ldg(xgr + 1024);
        float xgc = __ldg(xgr + 1536);

        __syncthreads();   // A: all warps done reading HH(s-1)

        {   // fill: poll own tagged words until tag == s-1, pack fp16 -> HH
            const uint4* src4 = (const uint4*)(g_H32[(s + 1) & 1]
                                 + ((size_t)(bg * 16 + frow) << 9) + fch);
            unsigned te = (unsigned)((s - 1) & 0xffff);
            uint4 v[8];
#pragma unroll
            for (int q = 0; q < 8; q++) v[q] = make_uint4(0, 0, 0, 0);
            unsigned need = 0xffu;
            while (true) {
#pragma unroll
                for (int q = 0; q < 8; q++) {
                    if (need & (1u << q)) {
                        uint4 t4 = __ldcg(src4 + q);
                        if ((t4.x >> 16) == te && (t4.y >> 16) == te &&
                            (t4.z >> 16) == te && (t4.w >> 16) == te) {
                            v[q] = t4;
                            need &= ~(1u << q);
                        }
                    }
                }
                if (!need || --fuse <= 0) break;
            }
#pragma unroll
            for (int q = 0; q < 8; q++) {
                uint2 pp;
                pp.x = (v[q].x & 0xffffu) | (v[q].y << 16);
                pp.y = (v[q].z & 0xffffu) | (v[q].w << 16);
                *(uint2*)(sm + (frow * WPAD + fch + q * 4) * 2) = pp;
            }
        }
        __syncthreads();   // B: HH complete before ldsm reads

        // full-K MMA: 16 double-tile ldsm4, 4 independent acc chains
        float acc[4][4];
#pragma unroll
        for (int c = 0; c < 4; c++)
#pragma unroll
            for (int q = 0; q < 4; q++) acc[c][q] = 0.f;
#pragma unroll
        for (int dt = 0; dt < 16; dt++) {
            uint32_t bf[4];
            ldsm4(bf, bB + dt * 64);
            mma16816h(acc[(dt & 1) * 2],     areg[2 * dt],     bf);
            mma16816h(acc[(dt & 1) * 2 + 1], areg[2 * dt + 1], bf + 2);
        }
        float d0 = acc[0][0] + acc[1][0] + acc[2][0] + acc[3][0];
        float d1 = acc[0][1] + acc[1][1] + acc[2][1] + acc[3][1];
        float d2 = acc[0][2] + acc[1][2] + acc[2][2] + acc[3][2];
        float d3 = acc[0][3] + acc[1][3] + acc[2][3] + acc[3][3];

        // warp-private transpose: fragment -> per-cell gates
        scr[rr * 9 + cc]           = d0;
        scr[rr * 9 + cc + 1]       = d1;
        scr[(rr + 8) * 9 + cc]     = d2;
        scr[(rr + 8) * 9 + cc + 1] = d3;
        __syncwarp();

        {   // pointwise: rows r' = jlq*4 + {i,f,o,c}
            float gi = scr[(jlq * 4 + 0) * 9 + bq] + xgi;
            float gf = scr[(jlq * 4 + 1) * 9 + bq] + xgf;
            float go = scr[(jlq * 4 + 2) * 9 + bq] + xgo;
            float gc = scr[(jlq * 4 + 3) * 9 + bq] + xgc;
            float iv = 1.f / (1.f + __expf(-gi));
            float fv = 1.f / (1.f + __expf(-gf));
            float ov = 1.f / (1.f + __expf(-go));
            float gv = tanh_fast(gc);
            c_reg = fv * c_reg + iv * gv;
            float hv = ov * tanh_fast(c_reg);

            __half hh = __float2half_rn(hv);
            unsigned short us;
            memcpy(&us, &hh, 2);
            uint32_t word = (uint32_t)us | ((uint32_t)(s & 0xffff) << 16);
            uint32_t* hdst = (s & 1) ? hdst1 : hdst0;
            asm volatile("st.global.cg.u32 [%0], %1;" :: "l"(hdst), "r"(word) : "memory");

            if (s == SQ - 1) {
                out[hwr]         = hv;
                out[32768 + hwr] = c_reg;
            }
        }
        __syncwarp();
    }
}

// ---------------- launch ----------------
extern "C" void kernel_launch(void* const* d_in, const int* in_sizes, int n_in,
                              void* d_out, int out_size)
{
    const float* x = (const float*)d_in[0];
    cudaFuncSetAttribute(lstm_hmma_kernel, cudaFuncAttributeMaxDynamicSharedMemorySize, LSMEM_BYTES);
    cudaFuncSetAttribute(xproj_hmma_kernel, cudaFuncAttributeMaxDynamicSharedMemorySize, XSMEM_BYTES);

    prep_kernel<<<6408, 256>>>(
        (const float*)d_in[1],  (const float*)d_in[2],  (const float*)d_in[3],  (const float*)d_in[4],
        (const float*)d_in[5],  (const float*)d_in[6],  (const float*)d_in[7],  (const float*)d_in[8],
        (const float*)d_in[9],  (const float*)d_in[10], (const float*)d_in[11], (const float*)d_in[12],
        (const float*)d_in[13], (const float*)d_in[14], (const float*)d_in[15], (const float*)d_in[16]);

    xsplit_kernel<<<16384, 256>>>(x);

    dim3 g1(16, 512);
    xproj_hmma_kernel<<<g1, 256, XSMEM_BYTES>>>();

    lstm_hmma_kernel<<<128, 256, LSMEM_BYTES>>>((float*)d_out);
}

// round 17
// speedup vs baseline: 1.5997x; 1.5997x over previous
#include <cuda_runtime.h>
#include <cuda_fp16.h>
#include <cstdint>
#include <cstring>

#define SQ 1024
#define BA 64
#define IN 256
#define HD 512
#define G4 2048
#define WPAD 520

// ---------------- device scratch ----------------
__device__ __align__(16) float g_BIAS[G4];
__device__ __align__(16) __half g_WXh[G4 * IN];            // [n][i] fp16
__device__ __align__(16) __half g_Xh[(size_t)65536 * IN];  // [m=(s<<6)|b][i] fp16
__device__ __align__(16) __half g_WHh[32 * 64 * 512];      // [hg][row=g*16+jl][k] fp16
__device__ __align__(16) float g_XG[(size_t)SQ * BA * G4];
__device__ __align__(16) uint32_t g_H32[2][BA * HD];       // tagged h: (tag<<16)|fp16

// ---------------- helpers ----------------
__device__ __forceinline__ uint32_t smem_u32(const void* p) {
    uint32_t a;
    asm("{ .reg .u64 t; cvta.to.shared.u64 t, %1; cvt.u32.u64 %0, t; }" : "=r"(a) : "l"(p));
    return a;
}
__device__ __forceinline__ void ldsm4(uint32_t* r, uint32_t a) {
    asm volatile("ldmatrix.sync.aligned.m8n8.x4.shared.b16 {%0,%1,%2,%3}, [%4];"
                 : "=r"(r[0]), "=r"(r[1]), "=r"(r[2]), "=r"(r[3]) : "r"(a));
}
__device__ __forceinline__ void ldsm2(uint32_t* r, uint32_t a) {
    asm volatile("ldmatrix.sync.aligned.m8n8.x2.shared.b16 {%0,%1}, [%2];"
                 : "=r"(r[0]), "=r"(r[1]) : "r"(a));
}
__device__ __forceinline__ void mma16816h(float* d, const uint32_t* a, const uint32_t* b) {
    asm volatile("mma.sync.aligned.m16n8k16.row.col.f32.f16.f16.f32 "
                 "{%0,%1,%2,%3}, {%4,%5,%6,%7}, {%8,%9}, {%0,%1,%2,%3};"
                 : "+f"(d[0]), "+f"(d[1]), "+f"(d[2]), "+f"(d[3])
                 : "r"(a[0]), "r"(a[1]), "r"(a[2]), "r"(a[3]), "r"(b[0]), "r"(b[1]));
}
__device__ __forceinline__ float tanh_fast(float x) {
    float t = __expf(2.f * x);
    return __fdividef(t - 1.f, t + 1.f);
}

// ---------------- prep ----------------
__global__ void prep_kernel(
    const float* Wxi, const float* bxi, const float* Whi, const float* bhi,
    const float* Wxf, const float* bxf, const float* Whf, const float* bhf,
    const float* Wxo, const float* bxo, const float* Who, const float* bho,
    const float* Wxc, const float* bxc, const float* Whc, const float* bhc)
{
    const float* Wx[4] = {Wxi, Wxf, Wxo, Wxc};
    const float* bx[4] = {bxi, bxf, bxo, bxc};
    const float* Wh[4] = {Whi, Whf, Who, Whc};
    const float* bh[4] = {bhi, bhf, bho, bhc};
    long idx = (long)blockIdx.x * 256 + threadIdx.x;

    if (idx < 524288L) {                       // WX fp16, [n][i]
        int i = (int)(idx & 255), n = (int)(idx >> 8);
        int g = n >> 9, j = n & 511;
        g_WXh[idx] = __float2half_rn(Wx[g][(size_t)j * IN + i]);
        return;
    }
    idx -= 524288L;
    if (idx < 2048L) {
        int g = (int)(idx >> 9), j = (int)(idx & 511);
        g_BIAS[idx] = bx[g][j] + bh[g][j];
        return;
    }
    idx -= 2048L;
    if (idx < 1048576L) {                      // WH fp16 (R13/R15 row layout)
        int k = (int)(idx & 511);
        int r = (int)((idx >> 9) & 63);
        int hg = (int)(idx >> 15);
        int g = r >> 4, j = hg * 16 + (r & 15);
        g_WHh[idx] = __float2half_rn(Wh[g][(size_t)j * HD + k]);
        return;
    }
    idx -= 1048576L;
    if (idx < 65536L) {                        // tag-init BOTH h buffers each launch
        ((uint32_t*)g_H32)[idx] = 0xFFFF0000u; // tag=0xFFFF, h=0
        return;
    }
}

// ---------------- x -> fp16, layout [(s<<6)|b][i] ----------------
__global__ __launch_bounds__(256) void xsplit_kernel(const float* __restrict__ x)
{
    long idx = (long)blockIdx.x * 256 + threadIdx.x;
    long e = idx * 4;
    int i = (int)(e & 255);
    int s = (int)((e >> 8) & 1023);
    int b = (int)(e >> 18);
    float4 v = __ldg((const float4*)(x + e));
    __half h[4] = {__float2half_rn(v.x), __float2half_rn(v.y),
                   __float2half_rn(v.z), __float2half_rn(v.w)};
    size_t off = (((size_t)((s << 6) | b)) << 8) + i;
    *(uint2*)(g_Xh + off) = *(uint2*)h;
}

// ---------------- xproj: single-term fp16 HMMA (proven R10) ----------------
#define XPAD 136
#define XS_A 0
#define XS_B (128 * XPAD * 2)
#define XSMEM_BYTES (2 * 128 * XPAD * 2)

__global__ __launch_bounds__(256, 1) void xproj_hmma_kernel()
{
    extern __shared__ char sm[];
    int tid = threadIdx.x;
    int wid = tid >> 5, lane = tid & 31;
    int n0 = blockIdx.x * 128, m0 = blockIdx.y * 128;
    int mh = wid & 1, nh = wid >> 1;

    uint32_t smb = smem_u32(sm);
    int arow = lane & 15, ak = (lane >= 16) ? 8 : 0;
    uint32_t aB = smb + XS_A + ((mh * 64 + arow) * XPAD + ak) * 2;
    int brow = lane & 7, bk = (lane & 8) ? 8 : 0;
    uint32_t bB = smb + XS_B + ((nh * 32 + brow) * XPAD + bk) * 2;

    float d[4][4][4];
#pragma unroll
    for (int mi = 0; mi < 4; mi++)
#pragma unroll
        for (int ni = 0; ni < 4; ni++)
#pragma unroll
            for (int q = 0; q < 4; q++) d[mi][ni][q] = 0.f;

    int fr = tid >> 1, fh = (tid & 1) * 64;
#pragma unroll
    for (int kc = 0; kc < 2; kc++) {
        int k0 = kc * 128;
        {
            const uint4* sa = (const uint4*)(g_Xh + (((size_t)(m0 + fr)) << 8) + k0 + fh);
            const uint4* sb = (const uint4*)(g_WXh + (((size_t)(n0 + fr)) << 8) + k0 + fh);
            uint4* da4 = (uint4*)(sm + XS_A + (fr * XPAD + fh) * 2);
            uint4* db4 = (uint4*)(sm + XS_B + (fr * XPAD + fh) * 2);
#pragma unroll
            for (int c = 0; c < 8; c++) {
                da4[c] = __ldg(sa + c);
                db4[c] = __ldg(sb + c);
            }
        }
        __syncthreads();
#pragma unroll
        for (int ks = 0; ks < 8; ks++) {
            uint32_t ko = (uint32_t)ks * 32;
            uint32_t ah[4][4], bh[4][2];
#pragma unroll
            for (int mi = 0; mi < 4; mi++)
                ldsm4(ah[mi], aB + mi * (16 * XPAD * 2) + ko);
#pragma unroll
            for (int ni = 0; ni < 4; ni++)
                ldsm2(bh[ni], bB + ni * (8 * XPAD * 2) + ko);
#pragma unroll
            for (int mi = 0; mi < 4; mi++)
#pragma unroll
                for (int ni = 0; ni < 4; ni++)
                    mma16816h(d[mi][ni], ah[mi], bh[ni]);
        }
        __syncthreads();
    }

    int row_l = lane >> 2, col_l = (lane & 3) * 2;
#pragma unroll
    for (int mi = 0; mi < 4; mi++)
#pragma unroll
        for (int ni = 0; ni < 4; ni++) {
            int gr = m0 + mh * 64 + mi * 16 + row_l;
            int gc = n0 + nh * 32 + ni * 8 + col_l;
            float2 bb = *(const float2*)(g_BIAS + gc);
            float* o = g_XG + (size_t)gr * G4 + gc;
            *(float2*)o = make_float2(d[mi][ni][0] + bb.x, d[mi][ni][1] + bb.y);
            *(float2*)(o + 8 * G4) = make_float2(d[mi][ni][2] + bb.x, d[mi][ni][3] + bb.y);
        }
}

// ---------------- lstm: R15 16-warp skeleton + tagged-h poll-fused fill ----------------
// 128 CTAs = 4 bg x 32 hg; 512 thr = 16 warps = 4 mw x 4 kh (R13 MMA mapping).
// Sync/step: tag-poll fused into fill (spread addresses) + 2 CTA barriers. No counters.
#define OFF_CRED (16 * WPAD * 2 + 64)
#define LSMEM_BYTES (64 * WPAD * 2)

__global__ __launch_bounds__(512, 1) void lstm_hmma_kernel(float* __restrict__ out)
{
    extern __shared__ char sm[];
    int tid = threadIdx.x;
    int wid = tid >> 5, lane = tid & 31;
    int bg = blockIdx.x >> 5;
    int hg = blockIdx.x & 31;
    int mw = wid & 3;            // M quarter (16 rows)
    int kh = wid >> 2;           // K quarter (128 k)

    {   // stage W [64][WPAD]
        int r = tid >> 3, part = tid & 7;
        const uint4* s4 = (const uint4*)(g_WHh + ((size_t)(hg * 64 + r) << 9) + part * 64);
        uint4* d4 = (uint4*)(sm + (r * WPAD + part * 64) * 2);
#pragma unroll
        for (int i = 0; i < 8; i++) d4[i] = s4[i];
    }
    __syncthreads();

    uint32_t smb = smem_u32(sm);
    uint32_t areg[8][4];
    {   // A frags -> registers (once)
        int arow = lane & 15, ako = (lane >= 16) ? 8 : 0;
        uint32_t aB = smb + ((mw * 16 + arow) * WPAD + kh * 128 + ako) * 2;
#pragma unroll
        for (int kt = 0; kt < 8; kt++) ldsm4(areg[kt], aB + kt * 32);
    }
    __syncthreads();   // staging region now reused as HH + Cred

    int brow = (lane & 7) | ((lane & 16) >> 1);
    int bko = (lane & 8) ? 8 : 0;
    uint32_t bB = smb + (brow * WPAD + kh * 128 + bko) * 2;

    float* Cred = (float*)(sm + OFF_CRED);     // [4][64*17]
    float* Credk = Cred + kh * (64 * 17);
    int drow = mw * 16 + (lane >> 2), dcol = (lane & 3) * 2;

    int jl = tid & 15, b = (tid >> 4) & 15;
    int hwr = (bg * 16 + b) * HD + hg * 16 + jl;
    uint32_t* hdst0 = &g_H32[0][hwr];
    uint32_t* hdst1 = &g_H32[1][hwr];
    float c_reg = 0.f;

    int frow = tid >> 5, fchw = (tid & 31) * 16;   // fill: 16 tagged words/thread
    long fuse = 20000000L;                          // lifetime poll budget

    for (int s = 0; s < SQ; s++) {
        float xgi, xgf, xgo, xgc;
        if (tid < 256) {   // xg prefetch, hidden behind tag-poll
            const float* xgr = g_XG + (((size_t)(s * 64 + bg * 16 + b)) << 11) + hg * 16 + jl;
            xgi = __ldg(xgr);
            xgf = __ldg(xgr + 512);
            xgo = __ldg(xgr + 1024);
            xgc = __ldg(xgr + 1536);
        }

        {   // poll-fused fill: wait for own 16 tagged words, pack fp16 -> HH
            const uint4* src4 = (const uint4*)(g_H32[(s + 1) & 1]
                                 + ((size_t)(bg * 16 + frow) << 9) + fchw);
            unsigned te = (unsigned)((s - 1) & 0xffff);
            uint4 v[4];
#pragma unroll
            for (int q = 0; q < 4; q++) v[q] = make_uint4(0, 0, 0, 0);
            unsigned need = 0xFu;
            do {
#pragma unroll
                for (int q = 0; q < 4; q++) {
                    if (need & (1u << q)) {
                        uint4 t4 = __ldcg(src4 + q);
                        if ((t4.x >> 16) == te && (t4.y >> 16) == te &&
                            (t4.z >> 16) == te && (t4.w >> 16) == te) {
                            v[q] = t4;
                            need &= ~(1u << q);
                        }
                    }
                }
            } while (need && --fuse > 0);
            uint32_t p[8];
#pragma unroll
            for (int q = 0; q < 4; q++) {
                p[2 * q]     = (v[q].x & 0xffffu) | (v[q].y << 16);
                p[2 * q + 1] = (v[q].z & 0xffffu) | (v[q].w << 16);
            }
            uint4* dst = (uint4*)(sm + (frow * WPAD + fchw) * 2);
            dst[0] = make_uint4(p[0], p[1], p[2], p[3]);
            dst[1] = make_uint4(p[4], p[5], p[6], p[7]);
        }
        __syncthreads();   // B: HH complete before ldsm reads

        float c0[4] = {0, 0, 0, 0}, c1[4] = {0, 0, 0, 0};
#pragma unroll
        for (int kt = 0; kt < 8; kt++) {
            uint32_t bf[4];
            ldsm4(bf, bB + kt * 32);
            mma16816h(c0, areg[kt], bf);
            mma16816h(c1, areg[kt], bf + 2);
        }
        Credk[drow * 17 + dcol]            = c0[0];
        Credk[drow * 17 + dcol + 1]        = c0[1];
        Credk[(drow + 8) * 17 + dcol]      = c0[2];
        Credk[(drow + 8) * 17 + dcol + 1]  = c0[3];
        Credk[drow * 17 + dcol + 8]        = c1[0];
        Credk[drow * 17 + dcol + 9]        = c1[1];
        Credk[(drow + 8) * 17 + dcol + 8]  = c1[2];
        Credk[(drow + 8) * 17 + dcol + 9]  = c1[3];
        __syncthreads();   // C: Cred complete; also closes HH-read WAR for next fill

        if (tid < 256) {
            float gi = xgi, gf = xgf, go = xgo, gc = xgc;
#pragma unroll
            for (int q = 0; q < 4; q++) {
                const float* cp = Cred + q * (64 * 17);
                gi += cp[jl * 17 + b];
                gf += cp[(16 + jl) * 17 + b];
                go += cp[(32 + jl) * 17 + b];
                gc += cp[(48 + jl) * 17 + b];
            }
            float iv = 1.f / (1.f + __expf(-gi));
            float fv = 1.f / (1.f + __expf(-gf));
            float ov = 1.f / (1.f + __expf(-go));
            float gv = tanh_fast(gc);
            c_reg = fv * c_reg + iv * gv;
            float hv = ov * tanh_fast(c_reg);

            __half hh = __float2half_rn(hv);
            unsigned short us;
            memcpy(&us, &hh, 2);
            uint32_t word = (uint32_t)us | ((uint32_t)(s & 0xffff) << 16);
            uint32_t* hdst = (s & 1) ? hdst1 : hdst0;
            asm volatile("st.global.cg.u32 [%0], %1;" :: "l"(hdst), "r"(word) : "memory");

            if (s == SQ - 1) {
                out[hwr]         = hv;
                out[32768 + hwr] = c_reg;
            }
        }
        // no trailing barrier: fill(s+1) only proceeds per-thread once its own
        // tagged words show s; Cred WAR closed by pointwise-before-B(s+1) order
        // via each warp's next-iteration fill + barrier B.
    }
}

// ---------------- launch ----------------
extern "C" void kernel_launch(void* const* d_in, const int* in_sizes, int n_in,
                              void* d_out, int out_size)
{
    const float* x = (const float*)d_in[0];
    cudaFuncSetAttribute(lstm_hmma_kernel, cudaFuncAttributeMaxDynamicSharedMemorySize, LSMEM_BYTES);
    cudaFuncSetAttribute(xproj_hmma_kernel, cudaFuncAttributeMaxDynamicSharedMemorySize, XSMEM_BYTES);

    prep_kernel<<<6408, 256>>>(
        (const float*)d_in[1],  (const float*)d_in[2],  (const float*)d_in[3],  (const float*)d_in[4],
        (const float*)d_in[5],  (const float*)d_in[6],  (const float*)d_in[7],  (const float*)d_in[8],
        (const float*)d_in[9],  (const float*)d_in[10], (const float*)d_in[11], (const float*)d_in[12],
        (const float*)d_in[13], (const float*)d_in[14], (const float*)d_in[15], (const float*)d_in[16]);

    xsplit_kernel<<<16384, 256>>>(x);

    dim3 g1(16, 512);
    xproj_hmma_kernel<<<g1, 256, XSMEM_BYTES>>>();

    lstm_hmma_kernel<<<128, 512, LSMEM_BYTES>>>((float*)d_out);
}